// round 14
// baseline (speedup 1.0000x reference)
#include <cuda_runtime.h>
#include <cuda_bf16.h>
#include <cuda_fp16.h>
#include <cstdint>

#define NEG_INF_F (-1000000.0f)

constexpr int Hh = 512, Sn = 256;           // H, Sq=Sp
constexpr int TQ = 64;                      // q rows per CTA

// ---- smem byte offsets (R10 layout) ----
constexpr int ATT = 0;                      // [64 m][256 k] fp16, row stride 528 = 33792 B
constexpr int SCR = 33792;                  // 34816-byte aliased scratch
//   phase1 (double buffered, 13056/buf): A_hi(16x144) A_lo(16x144) B(16x528)
constexpr int P1_ALO = 2304, P1_B = 4608, P1_BUF = 13056;
//   epilogue: SD2 float[64][68]=17408 at SCR, SQT at SCR+17408
constexpr int SQT_OFF = 17408;
constexpr int PMNEG = 68608;                // float[256]
constexpr int QMV   = 69632;                // float[64]
constexpr int RED1  = 69888;                // float[64][4]
constexpr int RED2  = 70912;                // float[64][4]
constexpr int SMEM_BYTES = 71936;

__device__ __forceinline__ uint32_t smem_u32(const void* p) {
    uint32_t a;
    asm("{ .reg .u64 t; cvta.to.shared.u64 t, %1; cvt.u32.u64 %0, t; }" : "=r"(a) : "l"(p));
    return a;
}
__device__ __forceinline__ void ldsm4(uint32_t a[4], uint32_t addr) {
    asm volatile("ldmatrix.sync.aligned.m8n8.x4.shared.b16 {%0,%1,%2,%3}, [%4];"
                 : "=r"(a[0]), "=r"(a[1]), "=r"(a[2]), "=r"(a[3]) : "r"(addr));
}
__device__ __forceinline__ void ldsm4t(uint32_t a[4], uint32_t addr) {
    asm volatile("ldmatrix.sync.aligned.m8n8.x4.trans.shared.b16 {%0,%1,%2,%3}, [%4];"
                 : "=r"(a[0]), "=r"(a[1]), "=r"(a[2]), "=r"(a[3]) : "r"(addr));
}
__device__ __forceinline__ void mma16816h(float d[4], const uint32_t a[4],
                                          uint32_t b0, uint32_t b1) {
    asm volatile("mma.sync.aligned.m16n8k16.row.col.f32.f16.f16.f32 "
                 "{%0,%1,%2,%3}, {%4,%5,%6,%7}, {%8,%9}, {%0,%1,%2,%3};"
                 : "+f"(d[0]), "+f"(d[1]), "+f"(d[2]), "+f"(d[3])
                 : "r"(a[0]), "r"(a[1]), "r"(a[2]), "r"(a[3]), "r"(b0), "r"(b1));
}
// fp16 pack of 4 floats (single plane)
__device__ __forceinline__ uint2 cvt4h(float4 v) {
    __half2 h01 = __float22half2_rn(make_float2(v.x, v.y));
    __half2 h23 = __float22half2_rn(make_float2(v.z, v.w));
    uint2 r;
    r.x = *reinterpret_cast<uint32_t*>(&h01);
    r.y = *reinterpret_cast<uint32_t*>(&h23);
    return r;
}
__device__ __forceinline__ uint32_t cvt2h(float2 v) {
    __half2 h = __float22half2_rn(v);
    return *reinterpret_cast<uint32_t*>(&h);
}
// fp16 2-way split of 4 floats (phase-1 Q)
__device__ __forceinline__ void split4h(float4 v, uint2& hi, uint2& lo) {
    __half2 h01 = __float22half2_rn(make_float2(v.x, v.y));
    __half2 h23 = __float22half2_rn(make_float2(v.z, v.w));
    float2 f01 = __half22float2(h01), f23 = __half22float2(h23);
    __half2 l01 = __float22half2_rn(make_float2(v.x - f01.x, v.y - f01.y));
    __half2 l23 = __float22half2_rn(make_float2(v.z - f23.x, v.w - f23.y));
    hi.x = *reinterpret_cast<uint32_t*>(&h01); hi.y = *reinterpret_cast<uint32_t*>(&h23);
    lo.x = *reinterpret_cast<uint32_t*>(&l01); lo.y = *reinterpret_cast<uint32_t*>(&l23);
}
__device__ __forceinline__ uint32_t pack2h(float v0, float v1) {
    __half2 h = __float22half2_rn(make_float2(v0, v1));
    return *reinterpret_cast<uint32_t*>(&h);
}

__global__ void __launch_bounds__(256, 2)
rml_mma_kernel(const float* __restrict__ Q, const float* __restrict__ P,
               const int* __restrict__ qmask, const int* __restrict__ pmask,
               float* __restrict__ out)
{
    extern __shared__ char smb[];
    const uint32_t sb = smem_u32(smb);
    float* smf = reinterpret_cast<float*>(smb);

    const int tid = threadIdx.x, lane = tid & 31, wid = tid >> 5;
    const int g = lane >> 2, c2 = lane & 3, sel = lane >> 3, r8 = lane & 7;
    const int wm = wid >> 2, wn = wid & 3;
    const int R0 = wm * 32, C0 = wn * 64;           // phase1 warp tile 32m x 64n
    const int b = blockIdx.x >> 2, q0 = (blockIdx.x & 3) * TQ;

    const float* Qb = Q + (size_t)b * Hh * Sn;
    const float* Pb = P + (size_t)b * Hh * Sn;

    smf[PMNEG/4 + tid] = pmask[b * Sn + tid] ? NEG_INF_F : 0.0f;
    if (tid < 64) smf[QMV/4 + tid] = qmask[b * Sn + q0 + tid] ? 1.0f : 0.0f;

    // lane-constant ldmatrix offsets
    const int arowA = (sel >> 1) * 8 + r8, acol8 = (sel & 1) * 8;   // phase1 A (trans, [k][m])
    const int browB = (sel & 1) * 8 + r8, bcol8 = (sel >> 1) * 8;   // phase1 B (trans, [k][n])
    const int p2Ar  = (sel & 1) * 8 + r8, p2Ac8 = (sel >> 1) * 8;   // phase2 A ([m][k])
    // phase2 B direct-gmem fragment addressing
    const int bln = lane >> 2;          // n (h row) within frag: 0..7
    const int blk = (lane & 3) * 2;     // k (p col) within chunk

    float acc[2][8][4];
#pragma unroll
    for (int a = 0; a < 2; a++)
#pragma unroll
        for (int c = 0; c < 8; c++)
#pragma unroll
            for (int j = 0; j < 4; j++) acc[a][c][j] = 0.0f;

    // -------- Phase 1: sim = Q^T @ P (Q split fp16 hi/lo, P fp16) ---------
    {
        int k = tid >> 4, u = tid & 15;
        float4 v = *(const float4*)(Qb + (size_t)k * Sn + q0 + 4 * u);
        uint2 hi, lo; split4h(v, hi, lo);
        *(uint2*)(smb + SCR + k * 144 + u * 8) = hi;
        *(uint2*)(smb + SCR + P1_ALO + k * 144 + u * 8) = lo;
#pragma unroll
        for (int i = 0; i < 4; i++) {
            int fl = i * 256 + tid, kk = fl >> 6, uu = fl & 63;
            float4 w = *(const float4*)(Pb + (size_t)kk * Sn + 4 * uu);
            *(uint2*)(smb + SCR + P1_B + kk * 528 + uu * 8) = cvt4h(w);
        }
    }
    __syncthreads();

    for (int kc = 0; kc < 32; ++kc) {
        const int cur = kc & 1;
        float4 va, vb[4];
        if (kc < 31) {
            const int h0n = (kc + 1) * 16;
            {
                int k = tid >> 4, u = tid & 15;
                va = *(const float4*)(Qb + (size_t)(h0n + k) * Sn + q0 + 4 * u);
            }
#pragma unroll
            for (int i = 0; i < 4; i++) {
                int fl = i * 256 + tid, k = fl >> 6, u = fl & 63;
                vb[i] = *(const float4*)(Pb + (size_t)(h0n + k) * Sn + 4 * u);
            }
        }

        const uint32_t abh = sb + SCR + cur * P1_BUF;
        const uint32_t abl = abh + P1_ALO;
        const uint32_t bbuf = abh + P1_B;

        uint32_t ah[2][4], al[2][4];
#pragma unroll
        for (int mf = 0; mf < 2; mf++) {
            uint32_t off = (uint32_t)(arowA * 144 + (R0 + mf * 16 + acol8) * 2);
            ldsm4t(ah[mf], abh + off);
            ldsm4t(al[mf], abl + off);
        }
#pragma unroll
        for (int nh = 0; nh < 4; nh++) {
            uint32_t off = (uint32_t)(browB * 528 + (C0 + nh * 16 + bcol8) * 2);
            uint32_t bh[4];
            ldsm4t(bh, bbuf + off);
#pragma unroll
            for (int mf = 0; mf < 2; mf++) {
                mma16816h(acc[mf][2*nh],   ah[mf], bh[0], bh[1]);
                mma16816h(acc[mf][2*nh],   al[mf], bh[0], bh[1]);
                mma16816h(acc[mf][2*nh+1], ah[mf], bh[2], bh[3]);
                mma16816h(acc[mf][2*nh+1], al[mf], bh[2], bh[3]);
            }
        }

        if (kc < 31) {
            const int baseo = SCR + (cur ^ 1) * P1_BUF;
            {
                int k = tid >> 4, u = tid & 15;
                uint2 hi, lo; split4h(va, hi, lo);
                *(uint2*)(smb + baseo + k * 144 + u * 8) = hi;
                *(uint2*)(smb + baseo + P1_ALO + k * 144 + u * 8) = lo;
            }
#pragma unroll
            for (int i = 0; i < 4; i++) {
                int fl = i * 256 + tid, k = fl >> 6, u = fl & 63;
                *(uint2*)(smb + baseo + P1_B + k * 528 + u * 8) = cvt4h(vb[i]);
            }
        }
        __syncthreads();
    }

    // ---------------- Softmax (registers + small smem reduce) -------------
    float pmb[8][2], qv[2][2];
#pragma unroll
    for (int nf = 0; nf < 8; nf++) {
        pmb[nf][0] = smf[PMNEG/4 + C0 + nf * 8 + 2 * c2];
        pmb[nf][1] = smf[PMNEG/4 + C0 + nf * 8 + 2 * c2 + 1];
    }
#pragma unroll
    for (int mf = 0; mf < 2; mf++) {
        qv[mf][0] = smf[QMV/4 + R0 + mf * 16 + g];
        qv[mf][1] = smf[QMV/4 + R0 + mf * 16 + g + 8];
    }
#pragma unroll
    for (int mf = 0; mf < 2; mf++)
#pragma unroll
        for (int h = 0; h < 2; h++) {
            float m = -3.4e38f;
#pragma unroll
            for (int nf = 0; nf < 8; nf++)
#pragma unroll
                for (int p = 0; p < 2; p++) {
                    float x = acc[mf][nf][2*h + p] + qv[mf][h] * pmb[nf][p];
                    acc[mf][nf][2*h + p] = x;
                    m = fmaxf(m, x);
                }
            m = fmaxf(m, __shfl_xor_sync(0xffffffffu, m, 1));
            m = fmaxf(m, __shfl_xor_sync(0xffffffffu, m, 2));
            if (c2 == 0) smf[RED1/4 + (R0 + mf * 16 + g + 8 * h) * 4 + wn] = m;
        }
    __syncthreads();
#pragma unroll
    for (int mf = 0; mf < 2; mf++)
#pragma unroll
        for (int h = 0; h < 2; h++) {
            const int row = R0 + mf * 16 + g + 8 * h;
            float m = fmaxf(fmaxf(smf[RED1/4 + row*4], smf[RED1/4 + row*4 + 1]),
                            fmaxf(smf[RED1/4 + row*4 + 2], smf[RED1/4 + row*4 + 3]));
            float s = 0.0f;
#pragma unroll
            for (int nf = 0; nf < 8; nf++)
#pragma unroll
                for (int p = 0; p < 2; p++) {
                    float e = __expf(acc[mf][nf][2*h + p] - m);
                    acc[mf][nf][2*h + p] = e;
                    s += e;
                }
            s += __shfl_xor_sync(0xffffffffu, s, 1);
            s += __shfl_xor_sync(0xffffffffu, s, 2);
            if (c2 == 0) smf[RED2/4 + row * 4 + wn] = s;
        }
    __syncthreads();
#pragma unroll
    for (int mf = 0; mf < 2; mf++)
#pragma unroll
        for (int h = 0; h < 2; h++) {
            const int row = R0 + mf * 16 + g + 8 * h;
            float s = smf[RED2/4 + row*4] + smf[RED2/4 + row*4 + 1] +
                      smf[RED2/4 + row*4 + 2] + smf[RED2/4 + row*4 + 3];
            const float inv = 1.0f / s;
#pragma unroll
            for (int nf = 0; nf < 8; nf++) {
                float v0 = acc[mf][nf][2*h]     * inv;
                float v1 = acc[mf][nf][2*h + 1] * inv;
                uint32_t off = (uint32_t)(row * 528 + (C0 + nf * 8 + 2 * c2) * 2);
                *(uint32_t*)(smb + ATT + off) = pack2h(v0, v1);   // fp16 attention
            }
        }
    __syncthreads();   // publishes ATT; phase-1 scratch free

    // ---- Phase 2: q_tilda = att @ P^T, B fragments direct from gmem ------
    const int C2_0 = wn * 16;            // 16 h cols per warp per tile
    const int j4 = tid & 15, fch = (tid >> 4) & 3, g2 = tid >> 6;   // g2 0..3
    const int mrow = tid & 63, qhalf = tid >> 6;                    // 0..3

#pragma unroll 1
    for (int t = 0; t < 8; ++t) {
        const int h0 = t * 64;

        float qtv[16];
#pragma unroll
        for (int j = 0; j < 16; j++)
            qtv[j] = Qb[(size_t)(h0 + qhalf * 16 + j) * Sn + q0 + mrow];

        float acc2[2][2][4];
#pragma unroll
        for (int a = 0; a < 2; a++)
#pragma unroll
            for (int c = 0; c < 2; c++)
#pragma unroll
                for (int j = 0; j < 4; j++) acc2[a][c][j] = 0.0f;

        // barrier-free k-loop: A from smem ATT (ldsm), B direct LDG+cvt
        const float* pw0 = Pb + (size_t)(h0 + C2_0 + bln) * Sn + blk;       // nf=0
        const float* pw1 = Pb + (size_t)(h0 + C2_0 + 8 + bln) * Sn + blk;   // nf=1
#pragma unroll 4
        for (int ks = 0; ks < 16; ++ks) {
            const int k0 = ks * 16;
            uint32_t ah2[2][4];
#pragma unroll
            for (int mf = 0; mf < 2; mf++) {
                uint32_t off = (uint32_t)((R0 + mf * 16 + p2Ar) * 528 + (k0 + p2Ac8) * 2);
                ldsm4(ah2[mf], sb + ATT + off);
            }
            float2 x00 = *(const float2*)(pw0 + k0);
            float2 x01 = *(const float2*)(pw0 + k0 + 8);
            float2 x10 = *(const float2*)(pw1 + k0);
            float2 x11 = *(const float2*)(pw1 + k0 + 8);
            uint32_t b00 = cvt2h(x00), b01 = cvt2h(x01);
            uint32_t b10 = cvt2h(x10), b11 = cvt2h(x11);
#pragma unroll
            for (int mf = 0; mf < 2; mf++) {
                mma16816h(acc2[mf][0], ah2[mf], b00, b01);
                mma16816h(acc2[mf][1], ah2[mf], b10, b11);
            }
        }

        // epilogue: protect SCR from previous tile's readers, then stage
        __syncthreads();
#pragma unroll
        for (int mf = 0; mf < 2; mf++)
#pragma unroll
            for (int nf = 0; nf < 2; nf++)
#pragma unroll
                for (int h = 0; h < 2; h++) {
                    const int row = R0 + mf * 16 + g + 8 * h;
                    const int col = C2_0 + nf * 8 + 2 * c2;
                    *(float2*)(smf + SCR/4 + row * 68 + col) =
                        make_float2(acc2[mf][nf][2*h], acc2[mf][nf][2*h + 1]);
                }
#pragma unroll
        for (int j = 0; j < 16; j++)
            smf[SCR/4 + SQT_OFF/4 + mrow * 68 + qhalf * 16 + j] = qtv[j];
        __syncthreads();

        // concat write: [q_t, q_tilda, q_t - q_tilda, q_t * q_tilda]
#pragma unroll 4
        for (int mp = 0; mp < 16; mp++) {
            const int mm = mp * 4 + g2;
            float4 qt = *(const float4*)(smf + SCR/4 + SQT_OFF/4 + mm * 68 + j4 * 4);
            float4 td = *(const float4*)(smf + SCR/4 + mm * 68 + j4 * 4);
            float4 o;
            if      (fch == 0) o = qt;
            else if (fch == 1) o = td;
            else if (fch == 2) o = make_float4(qt.x - td.x, qt.y - td.y, qt.z - td.z, qt.w - td.w);
            else               o = make_float4(qt.x * td.x, qt.y * td.y, qt.z * td.z, qt.w * td.w);
            *(float4*)(out + ((size_t)(b * Sn + q0 + mm)) * 2048 + fch * 512 + h0 + j4 * 4) = o;
        }
    }
}

extern "C" void kernel_launch(void* const* d_in, const int* in_sizes, int n_in,
                              void* d_out, int out_size)
{
    const float* Q  = (const float*)d_in[0];
    const float* P  = (const float*)d_in[1];
    const int*   qm = (const int*)d_in[2];
    const int*   pm = (const int*)d_in[3];
    float*       O  = (float*)d_out;

    cudaFuncSetAttribute(rml_mma_kernel,
                         cudaFuncAttributeMaxDynamicSharedMemorySize, SMEM_BYTES);

    rml_mma_kernel<<<1024, 256, SMEM_BYTES>>>(Q, P, qm, pm, O);
}

// round 15
// speedup vs baseline: 1.8379x; 1.8379x over previous
#include <cuda_runtime.h>
#include <cuda_bf16.h>
#include <cuda_fp16.h>
#include <cstdint>

#define NEG_INF_F (-1000000.0f)

constexpr int Hh = 512, Sn = 256;           // H, Sq=Sp
constexpr int TQ = 64;                      // q rows per CTA

// ---- smem byte offsets ----
constexpr int ATT = 0;                      // [64 m][256 k] fp16, row stride 528 = 33792 B
constexpr int SCR = 33792;                  // 34816-byte aliased scratch
//   phase1 (double buffered, 13056/buf): A_hi(16x144) A_lo(16x144) B(16x528)
constexpr int P1_ALO = 2304, P1_B = 4608, P1_BUF = 13056;
//   phase2: B2 double buffer, 2 x 17408 = 34816 (fills SCR exactly)
constexpr int PMNEG = 68608;                // float[256]
constexpr int QMV   = 69632;                // float[64]
constexpr int RED1  = 69888;                // float[64][4]
constexpr int RED2  = 70912;                // float[64][4]
constexpr int SMEM_BYTES = 71936;

__device__ __forceinline__ uint32_t smem_u32(const void* p) {
    uint32_t a;
    asm("{ .reg .u64 t; cvta.to.shared.u64 t, %1; cvt.u32.u64 %0, t; }" : "=r"(a) : "l"(p));
    return a;
}
__device__ __forceinline__ void ldsm4(uint32_t a[4], uint32_t addr) {
    asm volatile("ldmatrix.sync.aligned.m8n8.x4.shared.b16 {%0,%1,%2,%3}, [%4];"
                 : "=r"(a[0]), "=r"(a[1]), "=r"(a[2]), "=r"(a[3]) : "r"(addr));
}
__device__ __forceinline__ void ldsm4t(uint32_t a[4], uint32_t addr) {
    asm volatile("ldmatrix.sync.aligned.m8n8.x4.trans.shared.b16 {%0,%1,%2,%3}, [%4];"
                 : "=r"(a[0]), "=r"(a[1]), "=r"(a[2]), "=r"(a[3]) : "r"(addr));
}
__device__ __forceinline__ void mma16816h(float d[4], const uint32_t a[4],
                                          uint32_t b0, uint32_t b1) {
    asm volatile("mma.sync.aligned.m16n8k16.row.col.f32.f16.f16.f32 "
                 "{%0,%1,%2,%3}, {%4,%5,%6,%7}, {%8,%9}, {%0,%1,%2,%3};"
                 : "+f"(d[0]), "+f"(d[1]), "+f"(d[2]), "+f"(d[3])
                 : "r"(a[0]), "r"(a[1]), "r"(a[2]), "r"(a[3]), "r"(b0), "r"(b1));
}
// fp16 pack of 4 floats (single plane)
__device__ __forceinline__ uint2 cvt4h(float4 v) {
    __half2 h01 = __float22half2_rn(make_float2(v.x, v.y));
    __half2 h23 = __float22half2_rn(make_float2(v.z, v.w));
    uint2 r;
    r.x = *reinterpret_cast<uint32_t*>(&h01);
    r.y = *reinterpret_cast<uint32_t*>(&h23);
    return r;
}
// fp16 2-way split of 4 floats (phase-1 Q)
__device__ __forceinline__ void split4h(float4 v, uint2& hi, uint2& lo) {
    __half2 h01 = __float22half2_rn(make_float2(v.x, v.y));
    __half2 h23 = __float22half2_rn(make_float2(v.z, v.w));
    float2 f01 = __half22float2(h01), f23 = __half22float2(h23);
    __half2 l01 = __float22half2_rn(make_float2(v.x - f01.x, v.y - f01.y));
    __half2 l23 = __float22half2_rn(make_float2(v.z - f23.x, v.w - f23.y));
    hi.x = *reinterpret_cast<uint32_t*>(&h01); hi.y = *reinterpret_cast<uint32_t*>(&h23);
    lo.x = *reinterpret_cast<uint32_t*>(&l01); lo.y = *reinterpret_cast<uint32_t*>(&l23);
}
__device__ __forceinline__ uint32_t pack2h(float v0, float v1) {
    __half2 h = __float22half2_rn(make_float2(v0, v1));
    return *reinterpret_cast<uint32_t*>(&h);
}

__global__ void __launch_bounds__(256, 2)
rml_mma_kernel(const float* __restrict__ Q, const float* __restrict__ P,
               const int* __restrict__ qmask, const int* __restrict__ pmask,
               float* __restrict__ out)
{
    extern __shared__ char smb[];
    const uint32_t sb = smem_u32(smb);
    float* smf = reinterpret_cast<float*>(smb);

    const int tid = threadIdx.x, lane = tid & 31, wid = tid >> 5;
    const int g = lane >> 2, c2 = lane & 3, sel = lane >> 3, r8 = lane & 7;
    const int wm = wid >> 2, wn = wid & 3;
    const int R0 = wm * 32, C0 = wn * 64;           // phase1 warp tile 32m x 64n
    const int b = blockIdx.x >> 2, q0 = (blockIdx.x & 3) * TQ;

    const float* Qb = Q + (size_t)b * Hh * Sn;
    const float* Pb = P + (size_t)b * Hh * Sn;

    smf[PMNEG/4 + tid] = pmask[b * Sn + tid] ? NEG_INF_F : 0.0f;
    if (tid < 64) smf[QMV/4 + tid] = qmask[b * Sn + q0 + tid] ? 1.0f : 0.0f;

    // lane-constant ldmatrix offsets
    const int arowA = (sel >> 1) * 8 + r8, acol8 = (sel & 1) * 8;   // phase1 A (trans, [k][m])
    const int browB = (sel & 1) * 8 + r8, bcol8 = (sel >> 1) * 8;   // phase1 B (trans, [k][n])
    const int p2Ar  = (sel & 1) * 8 + r8, p2Ac8 = (sel >> 1) * 8;   // phase2 A ([m][k])
    const int p2Br  = (sel >> 1) * 8 + r8, p2Bc8 = (sel & 1) * 8;   // phase2 B ([n][k])

    float acc[2][8][4];
#pragma unroll
    for (int a = 0; a < 2; a++)
#pragma unroll
        for (int c = 0; c < 8; c++)
#pragma unroll
            for (int j = 0; j < 4; j++) acc[a][c][j] = 0.0f;

    // -------- Phase 1: sim = Q^T @ P (Q split fp16 hi/lo, P fp16) ---------
    {
        int k = tid >> 4, u = tid & 15;
        float4 v = *(const float4*)(Qb + (size_t)k * Sn + q0 + 4 * u);
        uint2 hi, lo; split4h(v, hi, lo);
        *(uint2*)(smb + SCR + k * 144 + u * 8) = hi;
        *(uint2*)(smb + SCR + P1_ALO + k * 144 + u * 8) = lo;
#pragma unroll
        for (int i = 0; i < 4; i++) {
            int fl = i * 256 + tid, kk = fl >> 6, uu = fl & 63;
            float4 w = *(const float4*)(Pb + (size_t)kk * Sn + 4 * uu);
            *(uint2*)(smb + SCR + P1_B + kk * 528 + uu * 8) = cvt4h(w);
        }
    }
    __syncthreads();

    for (int kc = 0; kc < 32; ++kc) {
        const int cur = kc & 1;
        float4 va, vb[4];
        if (kc < 31) {
            const int h0n = (kc + 1) * 16;
            {
                int k = tid >> 4, u = tid & 15;
                va = *(const float4*)(Qb + (size_t)(h0n + k) * Sn + q0 + 4 * u);
            }
#pragma unroll
            for (int i = 0; i < 4; i++) {
                int fl = i * 256 + tid, k = fl >> 6, u = fl & 63;
                vb[i] = *(const float4*)(Pb + (size_t)(h0n + k) * Sn + 4 * u);
            }
        }

        const uint32_t abh = sb + SCR + cur * P1_BUF;
        const uint32_t abl = abh + P1_ALO;
        const uint32_t bbuf = abh + P1_B;

        uint32_t ah[2][4], al[2][4];
#pragma unroll
        for (int mf = 0; mf < 2; mf++) {
            uint32_t off = (uint32_t)(arowA * 144 + (R0 + mf * 16 + acol8) * 2);
            ldsm4t(ah[mf], abh + off);
            ldsm4t(al[mf], abl + off);
        }
#pragma unroll
        for (int nh = 0; nh < 4; nh++) {
            uint32_t off = (uint32_t)(browB * 528 + (C0 + nh * 16 + bcol8) * 2);
            uint32_t bh[4];
            ldsm4t(bh, bbuf + off);
#pragma unroll
            for (int mf = 0; mf < 2; mf++) {
                mma16816h(acc[mf][2*nh],   ah[mf], bh[0], bh[1]);
                mma16816h(acc[mf][2*nh],   al[mf], bh[0], bh[1]);
                mma16816h(acc[mf][2*nh+1], ah[mf], bh[2], bh[3]);
                mma16816h(acc[mf][2*nh+1], al[mf], bh[2], bh[3]);
            }
        }

        if (kc < 31) {
            const int baseo = SCR + (cur ^ 1) * P1_BUF;
            {
                int k = tid >> 4, u = tid & 15;
                uint2 hi, lo; split4h(va, hi, lo);
                *(uint2*)(smb + baseo + k * 144 + u * 8) = hi;
                *(uint2*)(smb + baseo + P1_ALO + k * 144 + u * 8) = lo;
            }
#pragma unroll
            for (int i = 0; i < 4; i++) {
                int fl = i * 256 + tid, k = fl >> 6, u = fl & 63;
                *(uint2*)(smb + baseo + P1_B + k * 528 + u * 8) = cvt4h(vb[i]);
            }
        }
        __syncthreads();
    }

    // ---------------- Softmax (registers + small smem reduce) -------------
    float pmb[8][2], qv[2][2];
#pragma unroll
    for (int nf = 0; nf < 8; nf++) {
        pmb[nf][0] = smf[PMNEG/4 + C0 + nf * 8 + 2 * c2];
        pmb[nf][1] = smf[PMNEG/4 + C0 + nf * 8 + 2 * c2 + 1];
    }
#pragma unroll
    for (int mf = 0; mf < 2; mf++) {
        qv[mf][0] = smf[QMV/4 + R0 + mf * 16 + g];
        qv[mf][1] = smf[QMV/4 + R0 + mf * 16 + g + 8];
    }
#pragma unroll
    for (int mf = 0; mf < 2; mf++)
#pragma unroll
        for (int h = 0; h < 2; h++) {
            float m = -3.4e38f;
#pragma unroll
            for (int nf = 0; nf < 8; nf++)
#pragma unroll
                for (int p = 0; p < 2; p++) {
                    float x = acc[mf][nf][2*h + p] + qv[mf][h] * pmb[nf][p];
                    acc[mf][nf][2*h + p] = x;
                    m = fmaxf(m, x);
                }
            m = fmaxf(m, __shfl_xor_sync(0xffffffffu, m, 1));
            m = fmaxf(m, __shfl_xor_sync(0xffffffffu, m, 2));
            if (c2 == 0) smf[RED1/4 + (R0 + mf * 16 + g + 8 * h) * 4 + wn] = m;
        }
    __syncthreads();
#pragma unroll
    for (int mf = 0; mf < 2; mf++)
#pragma unroll
        for (int h = 0; h < 2; h++) {
            const int row = R0 + mf * 16 + g + 8 * h;
            float m = fmaxf(fmaxf(smf[RED1/4 + row*4], smf[RED1/4 + row*4 + 1]),
                            fmaxf(smf[RED1/4 + row*4 + 2], smf[RED1/4 + row*4 + 3]));
            float s = 0.0f;
#pragma unroll
            for (int nf = 0; nf < 8; nf++)
#pragma unroll
                for (int p = 0; p < 2; p++) {
                    float e = __expf(acc[mf][nf][2*h + p] - m);
                    acc[mf][nf][2*h + p] = e;
                    s += e;
                }
            s += __shfl_xor_sync(0xffffffffu, s, 1);
            s += __shfl_xor_sync(0xffffffffu, s, 2);
            if (c2 == 0) smf[RED2/4 + row * 4 + wn] = s;
        }
    __syncthreads();
#pragma unroll
    for (int mf = 0; mf < 2; mf++)
#pragma unroll
        for (int h = 0; h < 2; h++) {
            const int row = R0 + mf * 16 + g + 8 * h;
            float s = smf[RED2/4 + row*4] + smf[RED2/4 + row*4 + 1] +
                      smf[RED2/4 + row*4 + 2] + smf[RED2/4 + row*4 + 3];
            const float inv = 1.0f / s;
#pragma unroll
            for (int nf = 0; nf < 8; nf++) {
                float v0 = acc[mf][nf][2*h]     * inv;
                float v1 = acc[mf][nf][2*h + 1] * inv;
                uint32_t off = (uint32_t)(row * 528 + (C0 + nf * 8 + 2 * c2) * 2);
                *(uint32_t*)(smb + ATT + off) = pack2h(v0, v1);   // fp16 attention
            }
        }

    // -------- Phase 2: att @ P^T, dbl-buffered B2, smem-free epilogue -----
    const int C2_0 = wn * 16;            // 16 h cols per warp per tile

    // stage chunk 0 into buf0 (SCR free: last phase-1 reads were pre-sync)
    float4 vb2[8];
#pragma unroll
    for (int i = 0; i < 8; i++) {
        int fl = i * 256 + tid, n = fl >> 5, u = fl & 31;
        vb2[i] = *(const float4*)(Pb + (size_t)n * Sn + 4 * u);
    }
#pragma unroll
    for (int i = 0; i < 8; i++) {
        int fl = i * 256 + tid, n = fl >> 5, u = fl & 31;
        *(uint2*)(smb + SCR + n * 272 + u * 8) = cvt4h(vb2[i]);
    }
#pragma unroll
    for (int i = 0; i < 8; i++) {
        int fl = i * 256 + tid, n = fl >> 5, u = fl & 31;
        vb2[i] = *(const float4*)(Pb + (size_t)n * Sn + 128 + 4 * u);
    }
    __syncthreads();   // publishes ATT and B2 buf0

    float acc2[2][2][4];
    float qtf[4][4];   // [row4 = mf*2+h][col4 = nf*2+p]

#pragma unroll 1
    for (int cc = 0; cc < 16; ++cc) {
        const int t = cc >> 1, cch = cc & 1;
        const int h0 = t * 64;
        const uint32_t bcur = sb + SCR + (cc & 1) * 17408;

        if (cch == 0) {
#pragma unroll
            for (int a = 0; a < 2; a++)
#pragma unroll
                for (int c = 0; c < 2; c++)
#pragma unroll
                    for (int j = 0; j < 4; j++) acc2[a][c][j] = 0.0f;
            // gather q_t fragment scalars (coalesced across g-lanes)
#pragma unroll
            for (int r4 = 0; r4 < 4; r4++) {
                const int row = R0 + (r4 >> 1) * 16 + g + 8 * (r4 & 1);
#pragma unroll
                for (int c4 = 0; c4 < 4; c4++) {
                    const int col = C2_0 + (c4 >> 1) * 8 + 2 * c2 + (c4 & 1);
                    qtf[r4][c4] = Qb[(size_t)(h0 + col) * Sn + q0 + row];
                }
            }
        }

        // stage next chunk into the other buffer (overlaps this chunk's MMAs)
        if (cc < 15) {
            char* bnxtp = smb + SCR + ((cc + 1) & 1) * 17408;
#pragma unroll
            for (int i = 0; i < 8; i++) {
                int fl = i * 256 + tid, n = fl >> 5, u = fl & 31;
                *(uint2*)(bnxtp + n * 272 + u * 8) = cvt4h(vb2[i]);
            }
        }
        // prefetch chunk cc+2
        if (cc < 14) {
            const int h0n = ((cc + 2) >> 1) * 64, k0n = ((cc + 2) & 1) * 128;
#pragma unroll
            for (int i = 0; i < 8; i++) {
                int fl = i * 256 + tid, n = fl >> 5, u = fl & 31;
                vb2[i] = *(const float4*)(Pb + (size_t)(h0n + n) * Sn + k0n + 4 * u);
            }
        }

        const int kg = cch * 128;
#pragma unroll 2
        for (int ks = 0; ks < 8; ++ks) {
            const int k0 = ks * 16;
            uint32_t ah2[2][4];
#pragma unroll
            for (int mf = 0; mf < 2; mf++) {
                uint32_t off = (uint32_t)((R0 + mf * 16 + p2Ar) * 528 + (kg + k0 + p2Ac8) * 2);
                ldsm4(ah2[mf], sb + ATT + off);
            }
            uint32_t bh[4];
            {
                uint32_t off = (uint32_t)((C2_0 + p2Br) * 272 + (k0 + p2Bc8) * 2);
                ldsm4(bh, bcur + off);
            }
#pragma unroll
            for (int mf = 0; mf < 2; mf++) {
                mma16816h(acc2[mf][0], ah2[mf], bh[0], bh[1]);
                mma16816h(acc2[mf][1], ah2[mf], bh[2], bh[3]);
            }
        }
        __syncthreads();   // publish next buf; allow buf reuse next iter

        if (cch == 1) {
            // smem-free epilogue: direct fragment writes, all 4 features
#pragma unroll
            for (int mf = 0; mf < 2; mf++)
#pragma unroll
                for (int h = 0; h < 2; h++) {
                    const int row = R0 + mf * 16 + g + 8 * h;
                    float* ob = out + ((size_t)(b * Sn + q0 + row)) * 2048 + h0;
                    const int r4 = mf * 2 + h;
#pragma unroll
                    for (int nf = 0; nf < 2; nf++) {
                        const int col = C2_0 + nf * 8 + 2 * c2;
                        const float td0 = acc2[mf][nf][2*h], td1 = acc2[mf][nf][2*h + 1];
                        const float qa = qtf[r4][nf*2], qb2 = qtf[r4][nf*2 + 1];
                        *(float2*)(ob + col)          = make_float2(qa, qb2);
                        *(float2*)(ob + 512 + col)    = make_float2(td0, td1);
                        *(float2*)(ob + 1024 + col)   = make_float2(qa - td0, qb2 - td1);
                        *(float2*)(ob + 1536 + col)   = make_float2(qa * td0, qb2 * td1);
                    }
                }
        }
    }
}

extern "C" void kernel_launch(void* const* d_in, const int* in_sizes, int n_in,
                              void* d_out, int out_size)
{
    const float* Q  = (const float*)d_in[0];
    const float* P  = (const float*)d_in[1];
    const int*   qm = (const int*)d_in[2];
    const int*   pm = (const int*)d_in[3];
    float*       O  = (float*)d_out;

    cudaFuncSetAttribute(rml_mma_kernel,
                         cudaFuncAttributeMaxDynamicSharedMemorySize, SMEM_BYTES);

    rml_mma_kernel<<<1024, 256, SMEM_BYTES>>>(Q, P, qm, pm, O);
}

// round 16
// speedup vs baseline: 1.9219x; 1.0457x over previous
#include <cuda_runtime.h>
#include <cuda_bf16.h>
#include <cuda_fp16.h>
#include <cstdint>

#define NEG_INF_F (-1000000.0f)

constexpr int Hh = 512, Sn = 256;           // H, Sq=Sp
constexpr int TQ = 64;                      // q rows per CTA

// ---- smem byte offsets (R10 layout) ----
constexpr int ATT = 0;                      // [64 m][256 k] fp16, row stride 528 = 33792 B
constexpr int SCR = 33792;                  // 34816-byte aliased scratch
//   phase1 (double buffered, 13056/buf): A_hi(16x144) A_lo(16x144) B(16x528)
constexpr int P1_ALO = 2304, P1_B = 4608, P1_BUF = 13056;
//   phase2: B2 chunk [64n][128k] fp16 stride 272 -> 17408 (single buffer)
constexpr int PMNEG = 68608;                // float[256]
constexpr int QMV   = 69632;                // float[64]
constexpr int RED1  = 69888;                // float[64][4]
constexpr int RED2  = 70912;                // float[64][4]
constexpr int SMEM_BYTES = 71936;

__device__ __forceinline__ uint32_t smem_u32(const void* p) {
    uint32_t a;
    asm("{ .reg .u64 t; cvta.to.shared.u64 t, %1; cvt.u32.u64 %0, t; }" : "=r"(a) : "l"(p));
    return a;
}
__device__ __forceinline__ void ldsm4(uint32_t a[4], uint32_t addr) {
    asm volatile("ldmatrix.sync.aligned.m8n8.x4.shared.b16 {%0,%1,%2,%3}, [%4];"
                 : "=r"(a[0]), "=r"(a[1]), "=r"(a[2]), "=r"(a[3]) : "r"(addr));
}
__device__ __forceinline__ void ldsm4t(uint32_t a[4], uint32_t addr) {
    asm volatile("ldmatrix.sync.aligned.m8n8.x4.trans.shared.b16 {%0,%1,%2,%3}, [%4];"
                 : "=r"(a[0]), "=r"(a[1]), "=r"(a[2]), "=r"(a[3]) : "r"(addr));
}
__device__ __forceinline__ void mma16816h(float d[4], const uint32_t a[4],
                                          uint32_t b0, uint32_t b1) {
    asm volatile("mma.sync.aligned.m16n8k16.row.col.f32.f16.f16.f32 "
                 "{%0,%1,%2,%3}, {%4,%5,%6,%7}, {%8,%9}, {%0,%1,%2,%3};"
                 : "+f"(d[0]), "+f"(d[1]), "+f"(d[2]), "+f"(d[3])
                 : "r"(a[0]), "r"(a[1]), "r"(a[2]), "r"(a[3]), "r"(b0), "r"(b1));
}
// fp16 pack of 4 floats (single plane)
__device__ __forceinline__ uint2 cvt4h(float4 v) {
    __half2 h01 = __float22half2_rn(make_float2(v.x, v.y));
    __half2 h23 = __float22half2_rn(make_float2(v.z, v.w));
    uint2 r;
    r.x = *reinterpret_cast<uint32_t*>(&h01);
    r.y = *reinterpret_cast<uint32_t*>(&h23);
    return r;
}
// fp16 2-way split of 4 floats (phase-1 Q)
__device__ __forceinline__ void split4h(float4 v, uint2& hi, uint2& lo) {
    __half2 h01 = __float22half2_rn(make_float2(v.x, v.y));
    __half2 h23 = __float22half2_rn(make_float2(v.z, v.w));
    float2 f01 = __half22float2(h01), f23 = __half22float2(h23);
    __half2 l01 = __float22half2_rn(make_float2(v.x - f01.x, v.y - f01.y));
    __half2 l23 = __float22half2_rn(make_float2(v.z - f23.x, v.w - f23.y));
    hi.x = *reinterpret_cast<uint32_t*>(&h01); hi.y = *reinterpret_cast<uint32_t*>(&h23);
    lo.x = *reinterpret_cast<uint32_t*>(&l01); lo.y = *reinterpret_cast<uint32_t*>(&l23);
}
__device__ __forceinline__ uint32_t pack2h(float v0, float v1) {
    __half2 h = __float22half2_rn(make_float2(v0, v1));
    return *reinterpret_cast<uint32_t*>(&h);
}

__global__ void __launch_bounds__(256, 2)
rml_mma_kernel(const float* __restrict__ Q, const float* __restrict__ P,
               const int* __restrict__ qmask, const int* __restrict__ pmask,
               float* __restrict__ out)
{
    extern __shared__ char smb[];
    const uint32_t sb = smem_u32(smb);
    float* smf = reinterpret_cast<float*>(smb);

    const int tid = threadIdx.x, lane = tid & 31, wid = tid >> 5;
    const int g = lane >> 2, c2 = lane & 3, sel = lane >> 3, r8 = lane & 7;
    const int wm = wid >> 2, wn = wid & 3;
    const int R0 = wm * 32, C0 = wn * 64;           // phase1 warp tile 32m x 64n
    const int b = blockIdx.x >> 2, q0 = (blockIdx.x & 3) * TQ;

    const float* Qb = Q + (size_t)b * Hh * Sn;
    const float* Pb = P + (size_t)b * Hh * Sn;

    smf[PMNEG/4 + tid] = pmask[b * Sn + tid] ? NEG_INF_F : 0.0f;
    if (tid < 64) smf[QMV/4 + tid] = qmask[b * Sn + q0 + tid] ? 1.0f : 0.0f;

    // lane-constant ldmatrix offsets
    const int arowA = (sel >> 1) * 8 + r8, acol8 = (sel & 1) * 8;   // phase1 A (trans, [k][m])
    const int browB = (sel & 1) * 8 + r8, bcol8 = (sel >> 1) * 8;   // phase1 B (trans, [k][n])
    const int p2Ar  = (sel & 1) * 8 + r8, p2Ac8 = (sel >> 1) * 8;   // phase2 A ([m][k])
    const int p2Br  = (sel >> 1) * 8 + r8, p2Bc8 = (sel & 1) * 8;   // phase2 B ([n][k])

    float acc[2][8][4];
#pragma unroll
    for (int a = 0; a < 2; a++)
#pragma unroll
        for (int c = 0; c < 8; c++)
#pragma unroll
            for (int j = 0; j < 4; j++) acc[a][c][j] = 0.0f;

    // -------- Phase 1: sim = Q^T @ P (Q split fp16 hi/lo, P fp16) ---------
    {
        int k = tid >> 4, u = tid & 15;
        float4 v = *(const float4*)(Qb + (size_t)k * Sn + q0 + 4 * u);
        uint2 hi, lo; split4h(v, hi, lo);
        *(uint2*)(smb + SCR + k * 144 + u * 8) = hi;
        *(uint2*)(smb + SCR + P1_ALO + k * 144 + u * 8) = lo;
#pragma unroll
        for (int i = 0; i < 4; i++) {
            int fl = i * 256 + tid, kk = fl >> 6, uu = fl & 63;
            float4 w = *(const float4*)(Pb + (size_t)kk * Sn + 4 * uu);
            *(uint2*)(smb + SCR + P1_B + kk * 528 + uu * 8) = cvt4h(w);
        }
    }
    __syncthreads();

    for (int kc = 0; kc < 32; ++kc) {
        const int cur = kc & 1;
        float4 va, vb[4];
        if (kc < 31) {
            const int h0n = (kc + 1) * 16;
            {
                int k = tid >> 4, u = tid & 15;
                va = *(const float4*)(Qb + (size_t)(h0n + k) * Sn + q0 + 4 * u);
            }
#pragma unroll
            for (int i = 0; i < 4; i++) {
                int fl = i * 256 + tid, k = fl >> 6, u = fl & 63;
                vb[i] = *(const float4*)(Pb + (size_t)(h0n + k) * Sn + 4 * u);
            }
        }

        const uint32_t abh = sb + SCR + cur * P1_BUF;
        const uint32_t abl = abh + P1_ALO;
        const uint32_t bbuf = abh + P1_B;

        uint32_t ah[2][4], al[2][4];
#pragma unroll
        for (int mf = 0; mf < 2; mf++) {
            uint32_t off = (uint32_t)(arowA * 144 + (R0 + mf * 16 + acol8) * 2);
            ldsm4t(ah[mf], abh + off);
            ldsm4t(al[mf], abl + off);
        }
#pragma unroll
        for (int nh = 0; nh < 4; nh++) {
            uint32_t off = (uint32_t)(browB * 528 + (C0 + nh * 16 + bcol8) * 2);
            uint32_t bh[4];
            ldsm4t(bh, bbuf + off);
#pragma unroll
            for (int mf = 0; mf < 2; mf++) {
                mma16816h(acc[mf][2*nh],   ah[mf], bh[0], bh[1]);
                mma16816h(acc[mf][2*nh],   al[mf], bh[0], bh[1]);
                mma16816h(acc[mf][2*nh+1], ah[mf], bh[2], bh[3]);
                mma16816h(acc[mf][2*nh+1], al[mf], bh[2], bh[3]);
            }
        }

        if (kc < 31) {
            const int baseo = SCR + (cur ^ 1) * P1_BUF;
            {
                int k = tid >> 4, u = tid & 15;
                uint2 hi, lo; split4h(va, hi, lo);
                *(uint2*)(smb + baseo + k * 144 + u * 8) = hi;
                *(uint2*)(smb + baseo + P1_ALO + k * 144 + u * 8) = lo;
            }
#pragma unroll
            for (int i = 0; i < 4; i++) {
                int fl = i * 256 + tid, k = fl >> 6, u = fl & 63;
                *(uint2*)(smb + baseo + P1_B + k * 528 + u * 8) = cvt4h(vb[i]);
            }
        }
        __syncthreads();
    }

    // ---------------- Softmax (registers + small smem reduce) -------------
    float pmb[8][2], qv[2][2];
#pragma unroll
    for (int nf = 0; nf < 8; nf++) {
        pmb[nf][0] = smf[PMNEG/4 + C0 + nf * 8 + 2 * c2];
        pmb[nf][1] = smf[PMNEG/4 + C0 + nf * 8 + 2 * c2 + 1];
    }
#pragma unroll
    for (int mf = 0; mf < 2; mf++) {
        qv[mf][0] = smf[QMV/4 + R0 + mf * 16 + g];
        qv[mf][1] = smf[QMV/4 + R0 + mf * 16 + g + 8];
    }
#pragma unroll
    for (int mf = 0; mf < 2; mf++)
#pragma unroll
        for (int h = 0; h < 2; h++) {
            float m = -3.4e38f;
#pragma unroll
            for (int nf = 0; nf < 8; nf++)
#pragma unroll
                for (int p = 0; p < 2; p++) {
                    float x = acc[mf][nf][2*h + p] + qv[mf][h] * pmb[nf][p];
                    acc[mf][nf][2*h + p] = x;
                    m = fmaxf(m, x);
                }
            m = fmaxf(m, __shfl_xor_sync(0xffffffffu, m, 1));
            m = fmaxf(m, __shfl_xor_sync(0xffffffffu, m, 2));
            if (c2 == 0) smf[RED1/4 + (R0 + mf * 16 + g + 8 * h) * 4 + wn] = m;
        }
    __syncthreads();
#pragma unroll
    for (int mf = 0; mf < 2; mf++)
#pragma unroll
        for (int h = 0; h < 2; h++) {
            const int row = R0 + mf * 16 + g + 8 * h;
            float m = fmaxf(fmaxf(smf[RED1/4 + row*4], smf[RED1/4 + row*4 + 1]),
                            fmaxf(smf[RED1/4 + row*4 + 2], smf[RED1/4 + row*4 + 3]));
            float s = 0.0f;
#pragma unroll
            for (int nf = 0; nf < 8; nf++)
#pragma unroll
                for (int p = 0; p < 2; p++) {
                    float e = __expf(acc[mf][nf][2*h + p] - m);
                    acc[mf][nf][2*h + p] = e;
                    s += e;
                }
            s += __shfl_xor_sync(0xffffffffu, s, 1);
            s += __shfl_xor_sync(0xffffffffu, s, 2);
            if (c2 == 0) smf[RED2/4 + row * 4 + wn] = s;
        }
    __syncthreads();
#pragma unroll
    for (int mf = 0; mf < 2; mf++)
#pragma unroll
        for (int h = 0; h < 2; h++) {
            const int row = R0 + mf * 16 + g + 8 * h;
            float s = smf[RED2/4 + row*4] + smf[RED2/4 + row*4 + 1] +
                      smf[RED2/4 + row*4 + 2] + smf[RED2/4 + row*4 + 3];
            const float inv = 1.0f / s;
#pragma unroll
            for (int nf = 0; nf < 8; nf++) {
                float v0 = acc[mf][nf][2*h]     * inv;
                float v1 = acc[mf][nf][2*h + 1] * inv;
                uint32_t off = (uint32_t)(row * 528 + (C0 + nf * 8 + 2 * c2) * 2);
                *(uint32_t*)(smb + ATT + off) = pack2h(v0, v1);   // fp16 attention
            }
        }

    // ---- Phase 2: att @ P^T, single-buffer B2, smem-free epilogue --------
    const int C2_0 = wn * 16;            // 16 h cols per warp per tile

    // prefetch chunk 0
    float4 vb2[8];
#pragma unroll
    for (int i = 0; i < 8; i++) {
        int fl = i * 256 + tid, n = fl >> 5, u = fl & 31;
        vb2[i] = *(const float4*)(Pb + (size_t)n * Sn + 4 * u);
    }

    float acc2[2][2][4];
    float qtf[4][4];   // [row4 = mf*2+h][col4 = nf*2+p]

#pragma unroll 1
    for (int cc = 0; cc < 16; ++cc) {
        const int t = cc >> 1, cch = cc & 1;
        const int h0 = t * 64;

        __syncthreads();   // B2 buffer free (prior chunk's ldsm done)
        // stage current chunk
#pragma unroll
        for (int i = 0; i < 8; i++) {
            int fl = i * 256 + tid, n = fl >> 5, u = fl & 31;
            *(uint2*)(smb + SCR + n * 272 + u * 8) = cvt4h(vb2[i]);
        }
        // prefetch next chunk
        if (cc < 15) {
            const int h0n = ((cc + 1) >> 1) * 64, k0n = ((cc + 1) & 1) * 128;
#pragma unroll
            for (int i = 0; i < 8; i++) {
                int fl = i * 256 + tid, n = fl >> 5, u = fl & 31;
                vb2[i] = *(const float4*)(Pb + (size_t)(h0n + n) * Sn + k0n + 4 * u);
            }
        }
        if (cch == 0) {
#pragma unroll
            for (int a = 0; a < 2; a++)
#pragma unroll
                for (int c = 0; c < 2; c++)
#pragma unroll
                    for (int j = 0; j < 4; j++) acc2[a][c][j] = 0.0f;
            // gather q_t fragment scalars (sector-aligned across g-lanes)
#pragma unroll
            for (int r4 = 0; r4 < 4; r4++) {
                const int row = R0 + (r4 >> 1) * 16 + g + 8 * (r4 & 1);
#pragma unroll
                for (int c4 = 0; c4 < 4; c4++) {
                    const int col = C2_0 + (c4 >> 1) * 8 + 2 * c2 + (c4 & 1);
                    qtf[r4][c4] = Qb[(size_t)(h0 + col) * Sn + q0 + row];
                }
            }
        }
        __syncthreads();   // publishes B2 buffer

        const int kg = cch * 128;
#pragma unroll 2
        for (int ks = 0; ks < 8; ++ks) {
            const int k0 = ks * 16;
            uint32_t ah2[2][4];
#pragma unroll
            for (int mf = 0; mf < 2; mf++) {
                uint32_t off = (uint32_t)((R0 + mf * 16 + p2Ar) * 528 + (kg + k0 + p2Ac8) * 2);
                ldsm4(ah2[mf], sb + ATT + off);
            }
            uint32_t bh[4];
            {
                uint32_t off = (uint32_t)((C2_0 + p2Br) * 272 + (k0 + p2Bc8) * 2);
                ldsm4(bh, sb + SCR + off);
            }
#pragma unroll
            for (int mf = 0; mf < 2; mf++) {
                mma16816h(acc2[mf][0], ah2[mf], bh[0], bh[1]);
                mma16816h(acc2[mf][1], ah2[mf], bh[2], bh[3]);
            }
        }

        if (cch == 1) {
            // smem-free epilogue: direct fragment writes, all 4 features
#pragma unroll
            for (int mf = 0; mf < 2; mf++)
#pragma unroll
                for (int h = 0; h < 2; h++) {
                    const int row = R0 + mf * 16 + g + 8 * h;
                    float* ob = out + ((size_t)(b * Sn + q0 + row)) * 2048 + h0;
                    const int r4 = mf * 2 + h;
#pragma unroll
                    for (int nf = 0; nf < 2; nf++) {
                        const int col = C2_0 + nf * 8 + 2 * c2;
                        const float td0 = acc2[mf][nf][2*h], td1 = acc2[mf][nf][2*h + 1];
                        const float qa = qtf[r4][nf*2], qb2 = qtf[r4][nf*2 + 1];
                        *(float2*)(ob + col)          = make_float2(qa, qb2);
                        *(float2*)(ob + 512 + col)    = make_float2(td0, td1);
                        *(float2*)(ob + 1024 + col)   = make_float2(qa - td0, qb2 - td1);
                        *(float2*)(ob + 1536 + col)   = make_float2(qa * td0, qb2 * td1);
                    }
                }
        }
    }
}

extern "C" void kernel_launch(void* const* d_in, const int* in_sizes, int n_in,
                              void* d_out, int out_size)
{
    const float* Q  = (const float*)d_in[0];
    const float* P  = (const float*)d_in[1];
    const int*   qm = (const int*)d_in[2];
    const int*   pm = (const int*)d_in[3];
    float*       O  = (float*)d_out;

    cudaFuncSetAttribute(rml_mma_kernel,
                         cudaFuncAttributeMaxDynamicSharedMemorySize, SMEM_BYTES);

    rml_mma_kernel<<<1024, 256, SMEM_BYTES>>>(Q, P, qm, pm, O);
}